// round 8
// baseline (speedup 1.0000x reference)
#include <cuda_runtime.h>
#include <math.h>

// Problem constants
#define B_  8
#define A_  6
#define QS_ 32
#define KS_ 1024
#define C_  256
#define H_  64
#define W_DIM 64
#define NSPAT (C_ * H_ * W_DIM)            // 1048576 per (b, agent)
#define N4 (NSPAT / 4)                     // 262144 float4 per (b, agent)
#define OUT_MAIN ((size_t)B_ * A_ * NSPAT) // 50331648

#define ATTN_BLOCKS 8
#define COMBINE_BLOCKS (N4 * B_ / 256)     // 8192
#define TOTAL_BLOCKS (ATTN_BLOCKS + COMBINE_BLOCKS)

// Allocation-free scratch (device globals, zero-init; reset each run)
__device__ float g_attn[B_ * A_ * A_];     // softmaxed attention [B][K][Q]
__device__ int   g_flag;                   // # of batches whose attn is ready
__device__ int   g_done;                   // block arrival counter (for reset)

// --------------------------------------------------------------------------
// Single fused kernel.
//   Blocks 0..7   : attention (scores + softmax) for batch b = bid.
//   Blocks 8..end : combine  out[b,q,x] = sum_k attn[b,k,q] * v[b,k,x].
// Combine blocks issue their 6 streaming v loads BEFORE waiting on the
// attention flag, so the attn computation is hidden under the DRAM ramp.
// --------------------------------------------------------------------------
__global__ void __launch_bounds__(256)
fused_kernel(const float* __restrict__ qu,    // [B, A, QS]
             const float* __restrict__ kmat,  // [B, A, KS]
             const float4* __restrict__ v,    // [B, A, NSPAT] as float4
             const float* __restrict__ Wm,    // [KS, QS]
             const float* __restrict__ bias,  // [KS]
             float4* __restrict__ out,        // [B, A, NSPAT] as float4
             float* __restrict__ out_tail,    // [B, A, A]
             int write_tail) {
    const int bid = blockIdx.x;
    const int tid = threadIdx.x;

    if (bid < ATTN_BLOCKS) {
        // ------------------- ATTENTION (one block per batch) -------------------
        const int b    = bid;
        const int warp = tid >> 5;   // 0..7
        const int lane = tid & 31;

        __shared__ float s_k[A_ * KS_];          // 24 KB
        __shared__ float s_part[8][A_][QS_];     // 6 KB
        __shared__ float s_kp[A_][QS_];
        __shared__ float s_kb[A_];
        __shared__ float s_attn[A_ * A_];

        // Stage k[b] cooperatively (1536 float4, 6 per thread -> bulk MLP)
        {
            const float4* __restrict__ kg = (const float4*)(kmat + (size_t)b * A_ * KS_);
            float4* sk4 = (float4*)s_k;
            #pragma unroll
            for (int i = tid; i < A_ * KS_ / 4; i += 256) sk4[i] = kg[i];
        }
        __syncthreads();

        // Warp w owns d-range [128w, 128w+128) in 4 chunks of 32.
        {
            float acc[A_] = {0.f, 0.f, 0.f, 0.f, 0.f, 0.f};
            #pragma unroll
            for (int r = 0; r < 4; r++) {
                const int d0 = (warp * 4 + r) * 32;
                #pragma unroll 8
                for (int i = 0; i < 32; i++) {
                    const int d = d0 + i;
                    const float wv = Wm[(size_t)d * QS_ + lane];  // coalesced line
                    #pragma unroll
                    for (int kk = 0; kk < A_; kk++)
                        acc[kk] = fmaf(s_k[kk * KS_ + d], wv, acc[kk]);
                }
            }
            #pragma unroll
            for (int kk = 0; kk < A_; kk++)
                s_part[warp][kk][lane] = acc[kk];
        }

        // kb: warps 0..5 dot(k[kk], bias) from smem + coalesced bias
        if (warp < A_) {
            float s = 0.f;
            #pragma unroll 8
            for (int i = 0; i < KS_ / 32; i++) {
                const int d = lane + 32 * i;
                s = fmaf(s_k[warp * KS_ + d], bias[d], s);
            }
            #pragma unroll
            for (int off = 16; off; off >>= 1)
                s += __shfl_down_sync(0xffffffffu, s, off);
            if (lane == 0) s_kb[warp] = s;
        }
        __syncthreads();

        // Reduce 8 warp-partials -> kp[6][32]
        if (tid < A_ * QS_) {
            const int kk = tid >> 5, j = tid & 31;
            float acc = 0.f;
            #pragma unroll
            for (int w = 0; w < 8; w++) acc += s_part[w][kk][j];
            s_kp[kk][j] = acc;
        }
        __syncthreads();

        // scores[kk][qq] = kb[kk] + dot32(kp[kk], qu[b,qq,:])
        if (tid < A_ * A_) {
            const int kk = tid / A_, qq = tid % A_;
            const float* __restrict__ qrow = qu + ((size_t)b * A_ + qq) * QS_;
            float s = s_kb[kk];
            #pragma unroll
            for (int j = 0; j < QS_; j++) s = fmaf(s_kp[kk][j], qrow[j], s);
            s_attn[kk * A_ + qq] = s;
        }
        __syncthreads();

        // softmax over kk for each qq; publish with writer-side fence
        if (tid < A_) {
            const int qq = tid;
            float m = -INFINITY;
            #pragma unroll
            for (int kk = 0; kk < A_; kk++) m = fmaxf(m, s_attn[kk * A_ + qq]);
            float e[A_], sum = 0.f;
            #pragma unroll
            for (int kk = 0; kk < A_; kk++) {
                e[kk] = expf(s_attn[kk * A_ + qq] - m);
                sum += e[kk];
            }
            const float inv = 1.f / sum;
            #pragma unroll
            for (int kk = 0; kk < A_; kk++) {
                const float a = e[kk] * inv;
                g_attn[b * 36 + kk * A_ + qq] = a;
                if (write_tail) out_tail[b * 36 + kk * A_ + qq] = a;
            }
            __threadfence();   // writer-side: g_attn visible before flag
        }
        __syncthreads();
        if (tid == 0) atomicAdd(&g_flag, 1);

    } else {
        // ----------------------------- COMBINE -----------------------------
        const int chunk = bid - ATTN_BLOCKS;          // 0 .. 8191
        const int b = chunk >> 10;                    // / 1024
        const int x = (chunk & 1023) * 256 + tid;     // 0 .. N4-1

        // Issue the 6 streaming loads first (overlaps the attn blocks).
        float4 vv[A_];
        #pragma unroll
        for (int kk = 0; kk < A_; kk++)
            vv[kk] = v[((size_t)(b * A_ + kk)) * N4 + x];

        __shared__ float s_a[A_ * A_];
        if (tid < A_ * A_) {
            int f;
            do {
                asm volatile("ld.acquire.gpu.global.b32 %0, [%1];"
                             : "=r"(f) : "l"(&g_flag) : "memory");
            } while (f < B_);
            s_a[tid] = g_attn[b * 36 + tid];
        }
        __syncthreads();

        #pragma unroll
        for (int qq = 0; qq < A_; qq++) {
            float4 o = make_float4(0.f, 0.f, 0.f, 0.f);
            #pragma unroll
            for (int kk = 0; kk < A_; kk++) {
                const float a = s_a[kk * A_ + qq];
                o.x = fmaf(a, vv[kk].x, o.x);
                o.y = fmaf(a, vv[kk].y, o.y);
                o.z = fmaf(a, vv[kk].z, o.z);
                o.w = fmaf(a, vv[kk].w, o.w);
            }
            out[((size_t)(b * A_ + qq)) * N4 + x] = o;
        }
    }

    // ---- per-run reset so graph replays are deterministic ----
    __syncthreads();
    if (tid == 0) {
        const int d = atomicAdd(&g_done, 1);
        if (d == TOTAL_BLOCKS - 1) {   // last block to finish resets state
            g_flag = 0;
            g_done = 0;
            __threadfence();
        }
    }
}

extern "C" void kernel_launch(void* const* d_in, const int* in_sizes, int n_in,
                              void* d_out, int out_size) {
    const float* qu   = (const float*)d_in[0];   // [8,6,32]
    const float* kmat = (const float*)d_in[1];   // [8,6,1024]
    const float* v    = (const float*)d_in[2];   // [8,6,256,64,64]
    const float* Wm   = (const float*)d_in[3];   // [1024,32]
    const float* bias = (const float*)d_in[4];   // [1024]

    float* out = (float*)d_out;
    const int write_tail = ((size_t)out_size >= OUT_MAIN + (size_t)B_ * 36) ? 1 : 0;
    float* out_tail = out + OUT_MAIN;

    fused_kernel<<<TOTAL_BLOCKS, 256>>>(qu, kmat, (const float4*)v, Wm, bias,
                                        (float4*)out, out_tail, write_tail);
}

// round 9
// speedup vs baseline: 1.0268x; 1.0268x over previous
#include <cuda_runtime.h>
#include <math.h>

// Problem constants
#define B_  8
#define A_  6
#define QS_ 32
#define KS_ 1024
#define C_  256
#define H_  64
#define W_DIM 64
#define NSPAT (C_ * H_ * W_DIM)            // 1048576 per (b, agent)
#define N4 (NSPAT / 4)                     // 262144 float4 per (b, agent)
#define OUT_MAIN ((size_t)B_ * A_ * NSPAT) // 50331648

#define ATTN_BLOCKS 8
#define COMBINE_BLOCKS (N4 * B_ / 256)     // 8192
#define TOTAL_BLOCKS (ATTN_BLOCKS + COMBINE_BLOCKS)

// Allocation-free scratch (device globals, zero-init; reset by last block)
__device__ float g_attn[B_ * A_ * A_];     // softmaxed attention [B][K][Q]
__device__ int   g_flag;                   // # of batches whose attn is ready
__device__ int   g_done;                   // block arrival counter (for reset)

// --------------------------------------------------------------------------
// Single fused kernel.
//   Blocks 0..7   : attention (scores + softmax) for batch b = bid.
//   Blocks 8..end : combine  out[b,q,x] = sum_k attn[b,k,q] * v[b,k,x].
// Combine blocks issue their 6 streaming v loads BEFORE waiting; the wait is
// ONE thread per block polling with nanosleep backoff (no spin storm).
// --------------------------------------------------------------------------
__global__ void __launch_bounds__(256)
fused_kernel(const float* __restrict__ qu,    // [B, A, QS]
             const float* __restrict__ kmat,  // [B, A, KS]
             const float4* __restrict__ v,    // [B, A, NSPAT] as float4
             const float* __restrict__ Wm,    // [KS, QS]
             const float* __restrict__ bias,  // [KS]
             float4* __restrict__ out,        // [B, A, NSPAT] as float4
             float* __restrict__ out_tail,    // [B, A, A]
             int write_tail) {
    const int bid = blockIdx.x;
    const int tid = threadIdx.x;

    if (bid < ATTN_BLOCKS) {
        // ------------------- ATTENTION (one block per batch) -------------------
        const int b    = bid;
        const int warp = tid >> 5;   // 0..7
        const int lane = tid & 31;

        __shared__ float s_k[A_ * KS_];          // 24 KB
        __shared__ float s_part[8][A_][QS_];     // 6 KB
        __shared__ float s_kp[A_][QS_];
        __shared__ float s_kb[A_];
        __shared__ float s_attn[A_ * A_];

        // Stage k[b] cooperatively (1536 float4, 6 per thread -> bulk MLP)
        {
            const float4* __restrict__ kg = (const float4*)(kmat + (size_t)b * A_ * KS_);
            float4* sk4 = (float4*)s_k;
            #pragma unroll
            for (int i = tid; i < A_ * KS_ / 4; i += 256) sk4[i] = kg[i];
        }
        __syncthreads();

        // Warp w owns d-range [128w, 128w+128) in 4 chunks of 32.
        {
            float acc[A_] = {0.f, 0.f, 0.f, 0.f, 0.f, 0.f};
            #pragma unroll
            for (int r = 0; r < 4; r++) {
                const int d0 = (warp * 4 + r) * 32;
                #pragma unroll 8
                for (int i = 0; i < 32; i++) {
                    const int d = d0 + i;
                    const float wv = Wm[(size_t)d * QS_ + lane];  // coalesced line
                    #pragma unroll
                    for (int kk = 0; kk < A_; kk++)
                        acc[kk] = fmaf(s_k[kk * KS_ + d], wv, acc[kk]);
                }
            }
            #pragma unroll
            for (int kk = 0; kk < A_; kk++)
                s_part[warp][kk][lane] = acc[kk];
        }

        // kb: warps 0..5 dot(k[kk], bias) from smem + coalesced bias
        if (warp < A_) {
            float s = 0.f;
            #pragma unroll 8
            for (int i = 0; i < KS_ / 32; i++) {
                const int d = lane + 32 * i;
                s = fmaf(s_k[warp * KS_ + d], bias[d], s);
            }
            #pragma unroll
            for (int off = 16; off; off >>= 1)
                s += __shfl_down_sync(0xffffffffu, s, off);
            if (lane == 0) s_kb[warp] = s;
        }
        __syncthreads();

        // Reduce 8 warp-partials -> kp[6][32]
        if (tid < A_ * QS_) {
            const int kk = tid >> 5, j = tid & 31;
            float acc = 0.f;
            #pragma unroll
            for (int w = 0; w < 8; w++) acc += s_part[w][kk][j];
            s_kp[kk][j] = acc;
        }
        __syncthreads();

        // scores[kk][qq] = kb[kk] + dot32(kp[kk], qu[b,qq,:])
        if (tid < A_ * A_) {
            const int kk = tid / A_, qq = tid % A_;
            const float* __restrict__ qrow = qu + ((size_t)b * A_ + qq) * QS_;
            float s = s_kb[kk];
            #pragma unroll
            for (int j = 0; j < QS_; j++) s = fmaf(s_kp[kk][j], qrow[j], s);
            s_attn[kk * A_ + qq] = s;
        }
        __syncthreads();

        // softmax over kk for each qq; publish, then fence, then flag
        if (tid < A_) {
            const int qq = tid;
            float m = -INFINITY;
            #pragma unroll
            for (int kk = 0; kk < A_; kk++) m = fmaxf(m, s_attn[kk * A_ + qq]);
            float e[A_], sum = 0.f;
            #pragma unroll
            for (int kk = 0; kk < A_; kk++) {
                e[kk] = expf(s_attn[kk * A_ + qq] - m);
                sum += e[kk];
            }
            const float inv = 1.f / sum;
            #pragma unroll
            for (int kk = 0; kk < A_; kk++) {
                const float a = e[kk] * inv;
                g_attn[b * 36 + kk * A_ + qq] = a;
                if (write_tail) out_tail[b * 36 + kk * A_ + qq] = a;
            }
        }
        __syncthreads();
        if (tid == 0) {
            __threadfence();               // g_attn visible before flag bump
            atomicAdd(&g_flag, 1);
        }

    } else {
        // ----------------------------- COMBINE -----------------------------
        const int chunk = bid - ATTN_BLOCKS;          // 0 .. 8191
        const int b = chunk >> 10;                    // / 1024
        const int x = (chunk & 1023) * 256 + tid;     // 0 .. N4-1

        // Issue the 6 streaming loads first (overlaps the attn blocks).
        float4 vv[A_];
        #pragma unroll
        for (int kk = 0; kk < A_; kk++)
            vv[kk] = v[((size_t)(b * A_ + kk)) * N4 + x];

        // Low-traffic wait: single poller with sleep backoff.
        if (tid == 0) {
            int f;
            asm volatile("ld.acquire.gpu.global.b32 %0, [%1];"
                         : "=r"(f) : "l"(&g_flag) : "memory");
            while (f < B_) {
                __nanosleep(256);
                asm volatile("ld.acquire.gpu.global.b32 %0, [%1];"
                             : "=r"(f) : "l"(&g_flag) : "memory");
            }
        }
        __syncthreads();   // releases the block; orders g_attn reads after flag

        __shared__ float s_a[A_ * A_];
        if (tid < A_ * A_) s_a[tid] = g_attn[b * 36 + tid];
        __syncthreads();

        #pragma unroll
        for (int qq = 0; qq < A_; qq++) {
            float4 o = make_float4(0.f, 0.f, 0.f, 0.f);
            #pragma unroll
            for (int kk = 0; kk < A_; kk++) {
                const float a = s_a[kk * A_ + qq];
                o.x = fmaf(a, vv[kk].x, o.x);
                o.y = fmaf(a, vv[kk].y, o.y);
                o.z = fmaf(a, vv[kk].z, o.z);
                o.w = fmaf(a, vv[kk].w, o.w);
            }
            out[((size_t)(b * A_ + qq)) * N4 + x] = o;
        }
    }

    // ---- per-run reset so graph replays are deterministic ----
    __syncthreads();
    if (tid == 0) {
        const int d = atomicAdd(&g_done, 1);
        if (d == TOTAL_BLOCKS - 1) {   // last block to finish resets state
            g_flag = 0;
            g_done = 0;
            __threadfence();
        }
    }
}

extern "C" void kernel_launch(void* const* d_in, const int* in_sizes, int n_in,
                              void* d_out, int out_size) {
    const float* qu   = (const float*)d_in[0];   // [8,6,32]
    const float* kmat = (const float*)d_in[1];   // [8,6,1024]
    const float* v    = (const float*)d_in[2];   // [8,6,256,64,64]
    const float* Wm   = (const float*)d_in[3];   // [1024,32]
    const float* bias = (const float*)d_in[4];   // [1024]

    float* out = (float*)d_out;
    const int write_tail = ((size_t)out_size >= OUT_MAIN + (size_t)B_ * 36) ? 1 : 0;
    float* out_tail = out + OUT_MAIN;

    fused_kernel<<<TOTAL_BLOCKS, 256>>>(qu, kmat, (const float4*)v, Wm, bias,
                                        (float4*)out, out_tail, write_tail);
}

// round 10
// speedup vs baseline: 1.1548x; 1.1246x over previous
#include <cuda_runtime.h>
#include <math.h>

// Problem constants
#define B_  8
#define A_  6
#define QS_ 32
#define KS_ 1024
#define NSPAT (256 * 64 * 64)              // 1048576 per (b, agent)
#define N4 (NSPAT / 4)                     // 262144 float4 per (b, agent)
#define OUT_MAIN ((size_t)B_ * A_ * NSPAT) // 50331648

#define PARTS 8                            // d-slices per batch
#define DSL (KS_ / PARTS)                  // 128 d per slice

// Allocation-free scratch (device globals; counters reset by reducer)
__device__ float g_attn[B_ * A_ * A_];               // softmaxed attention
__device__ float g_kp_part[B_ * PARTS * A_ * QS_];   // per-slice kp partials
__device__ float g_kb_part[B_ * PARTS * A_];         // per-slice kb partials
__device__ int   g_cnt[B_];                          // per-batch arrival count

// --------------------------------------------------------------------------
// Primary kernel (PDL): 64 blocks = 8 batches x 8 d-slices, 256 threads.
// Each block: partial kp/kb over its 128-wide d-slice (one cold DRAM round).
// The 8th-arriving block per batch reduces partials (fixed order ->
// deterministic), computes scores + softmax, publishes g_attn.
// --------------------------------------------------------------------------
__global__ void __launch_bounds__(256)
attn_kernel(const float* __restrict__ qu,    // [B, A, QS]
            const float* __restrict__ kmat,  // [B, A, KS]
            const float* __restrict__ Wm,    // [KS, QS]
            const float* __restrict__ bias,  // [KS]
            float* __restrict__ out_tail,    // [B, A, A]
            int write_tail) {
    asm volatile("griddepcontrol.launch_dependents;");

    const int bid  = blockIdx.x;
    const int b    = bid >> 3;          // batch
    const int part = bid & 7;           // d-slice
    const int d0   = part * DSL;
    const int tid  = threadIdx.x;
    const int warp = tid >> 5;          // 0..7
    const int lane = tid & 31;

    __shared__ float s_k[A_][DSL];          // 3 KB: k slice
    __shared__ float s_part[8][A_][QS_];    // 6 KB: per-warp kp partials
    __shared__ float s_kbp[A_];
    __shared__ float s_kp[A_ * QS_];        // reducer stage
    __shared__ float s_kb[A_];
    __shared__ float s_attn[A_ * A_];
    __shared__ int   s_arrive;

    // Stage k slice: 6 rows x 128 floats = 192 float4 (1 per thread, tid<192)
    if (tid < A_ * DSL / 4) {
        const int kk = tid >> 5, i = tid & 31;   // 32 float4 per row
        ((float4*)s_k[kk])[i] =
            ((const float4*)kmat)[((size_t)b * A_ + kk) * (KS_ / 4) + part * (DSL / 4) + i];
    }
    __syncthreads();

    // Warp w handles 16 d-values: fully unrolled -> 16 outstanding W loads.
    {
        float acc[A_] = {0.f, 0.f, 0.f, 0.f, 0.f, 0.f};
        const int dl0 = warp * 16;
        #pragma unroll
        for (int i = 0; i < 16; i++) {
            const int dl = dl0 + i;
            const float wv = Wm[(size_t)(d0 + dl) * QS_ + lane];  // coalesced line
            #pragma unroll
            for (int kk = 0; kk < A_; kk++)
                acc[kk] = fmaf(s_k[kk][dl], wv, acc[kk]);
        }
        #pragma unroll
        for (int kk = 0; kk < A_; kk++)
            s_part[warp][kk][lane] = acc[kk];
    }

    // kb partial: warps 0..5, dot over the 128-wide slice (coalesced bias)
    if (warp < A_) {
        float s = 0.f;
        #pragma unroll
        for (int i = 0; i < DSL / 32; i++) {   // 4 iters
            const int dl = lane + 32 * i;
            s = fmaf(s_k[warp][dl], bias[d0 + dl], s);
        }
        #pragma unroll
        for (int off = 16; off; off >>= 1)
            s += __shfl_down_sync(0xffffffffu, s, off);
        if (lane == 0) s_kbp[warp] = s;
    }
    __syncthreads();

    // Block-level reduce of 8 warp partials -> publish slice partials
    if (tid < A_ * QS_) {
        const int kk = tid >> 5, j = tid & 31;
        float acc = 0.f;
        #pragma unroll
        for (int w = 0; w < 8; w++) acc += s_part[w][kk][j];
        g_kp_part[((size_t)(b * PARTS + part)) * (A_ * QS_) + tid] = acc;
    }
    if (tid < A_)
        g_kb_part[(b * PARTS + part) * A_ + tid] = s_kbp[tid];
    __threadfence();   // partials visible before the arrival bump
    __syncthreads();

    if (tid == 0) s_arrive = atomicAdd(&g_cnt[b], 1);
    __syncthreads();
    if (s_arrive != PARTS - 1) return;   // not the last slice for this batch

    // ---------------- Reducer (one block per batch) ----------------
    if (tid < A_ * QS_) {
        float acc = 0.f;
        #pragma unroll
        for (int p = 0; p < PARTS; p++)   // fixed order -> deterministic
            acc += g_kp_part[((size_t)(b * PARTS + p)) * (A_ * QS_) + tid];
        s_kp[tid] = acc;
    }
    if (tid < A_) {
        float acc = 0.f;
        #pragma unroll
        for (int p = 0; p < PARTS; p++)
            acc += g_kb_part[(b * PARTS + p) * A_ + tid];
        s_kb[tid] = acc;
    }
    __syncthreads();

    // scores[kk][qq] = kb[kk] + dot32(kp[kk], qu[b,qq,:])
    if (tid < A_ * A_) {
        const int kk = tid / A_, qq = tid % A_;
        const float* __restrict__ qrow = qu + ((size_t)b * A_ + qq) * QS_;
        float s = s_kb[kk];
        #pragma unroll
        for (int j = 0; j < QS_; j++) s = fmaf(s_kp[kk * QS_ + j], qrow[j], s);
        s_attn[kk * A_ + qq] = s;
    }
    __syncthreads();

    // softmax over kk for each qq; publish
    if (tid < A_) {
        const int qq = tid;
        float m = -INFINITY;
        #pragma unroll
        for (int kk = 0; kk < A_; kk++) m = fmaxf(m, s_attn[kk * A_ + qq]);
        float e[A_], sum = 0.f;
        #pragma unroll
        for (int kk = 0; kk < A_; kk++) {
            e[kk] = expf(s_attn[kk * A_ + qq] - m);
            sum += e[kk];
        }
        const float inv = 1.f / sum;
        #pragma unroll
        for (int kk = 0; kk < A_; kk++) {
            const float a = e[kk] * inv;
            g_attn[b * 36 + kk * A_ + qq] = a;
            if (write_tail) out_tail[b * 36 + kk * A_ + qq] = a;
        }
    }
    if (tid == 0) g_cnt[b] = 0;   // reset for next graph replay
}

// --------------------------------------------------------------------------
// Dependent kernel (PDL): out[b,q,x] = sum_k attn[b,k,q] * v[b,k,x].
// Plain loads (best measured), issued before griddepcontrol.wait so they
// overlap the attn kernel. 1 float4 per thread.
// --------------------------------------------------------------------------
__global__ void __launch_bounds__(256)
combine_kernel(const float4* __restrict__ v, float4* __restrict__ out) {
    const int b = blockIdx.y;
    const int x = blockIdx.x * blockDim.x + threadIdx.x;   // 0 .. N4-1

    // Independent prologue: issue the 6 streaming loads (overlap attn kernel).
    float4 vv[A_];
    #pragma unroll
    for (int kk = 0; kk < A_; kk++)
        vv[kk] = v[((size_t)(b * A_ + kk)) * N4 + x];

    asm volatile("griddepcontrol.wait;" ::: "memory");

    __shared__ float s_a[A_ * A_];
    if (threadIdx.x < A_ * A_) s_a[threadIdx.x] = g_attn[b * 36 + threadIdx.x];
    __syncthreads();

    #pragma unroll
    for (int qq = 0; qq < A_; qq++) {
        float4 o = make_float4(0.f, 0.f, 0.f, 0.f);
        #pragma unroll
        for (int kk = 0; kk < A_; kk++) {
            const float a = s_a[kk * A_ + qq];
            o.x = fmaf(a, vv[kk].x, o.x);
            o.y = fmaf(a, vv[kk].y, o.y);
            o.z = fmaf(a, vv[kk].z, o.z);
            o.w = fmaf(a, vv[kk].w, o.w);
        }
        out[((size_t)(b * A_ + qq)) * N4 + x] = o;
    }
}

extern "C" void kernel_launch(void* const* d_in, const int* in_sizes, int n_in,
                              void* d_out, int out_size) {
    const float* qu   = (const float*)d_in[0];   // [8,6,32]
    const float* kmat = (const float*)d_in[1];   // [8,6,1024]
    const float* v    = (const float*)d_in[2];   // [8,6,256,64,64]
    const float* Wm   = (const float*)d_in[3];   // [1024,32]
    const float* bias = (const float*)d_in[4];   // [1024]

    float* out = (float*)d_out;
    const int write_tail = ((size_t)out_size >= OUT_MAIN + (size_t)B_ * 36) ? 1 : 0;
    float* out_tail = out + OUT_MAIN;

    // Primary: attention, 64 blocks (signals dependents at start)
    attn_kernel<<<B_ * PARTS, 256>>>(qu, kmat, Wm, bias, out_tail, write_tail);

    // Dependent: combine with Programmatic Stream Serialization (PDL)
    cudaLaunchConfig_t cfg = {};
    cfg.gridDim  = dim3(N4 / 256, B_, 1);   // 1024 x 8 blocks
    cfg.blockDim = dim3(256, 1, 1);
    cfg.dynamicSmemBytes = 0;
    cfg.stream = 0;   // legacy default stream (the one under graph capture)
    cudaLaunchAttribute attr[1];
    attr[0].id = cudaLaunchAttributeProgrammaticStreamSerialization;
    attr[0].val.programmaticStreamSerializationAllowed = 1;
    cfg.attrs = attr;
    cfg.numAttrs = 1;
    cudaLaunchKernelEx(&cfg, combine_kernel, (const float4*)v, (float4*)out);
}